// round 8
// baseline (speedup 1.0000x reference)
#include <cuda_runtime.h>

// EfConv: out[n, k*64+o] = sum_{e: dst_e=n} ef[e,k] * (node_feat[src_e] . W[o]) + b[o]
// y = X @ W^T first (side stream). CSR-by-dst with 8-aligned segments, but the
// CSR payload is only (src, edge_id) int2 records; pads use src=N -> extra
// all-zero y row, eid=0 (exactly-zero contribution). k_main gathers ef rows
// directly (32B broadcast sectors, L2-resident). 4 launches total:
//   0 ygemm(s2, W-transpose fused)  1 build(hist+scan, grid-barrier)
//   2 scatter(records)              3 k_main  <- ncu capture slot

#define MAXN 50000
#define MAXE 800000
#define NF 64
#define ED 8
#define MAXP (MAXE + 8 * MAXN)
#define BLD_B 1024

typedef unsigned long long u64;

__device__ int   g_deg[MAXN];        // zeroed at load; re-zeroed by k_main epilog-for-next-call
__device__ int   g_off[MAXN + 1];
__device__ int   g_cur[MAXN];
__device__ int   g_bsum[64];
__device__ int   g_bar;              // monotonic grid-barrier counter (never reset)
__device__ __align__(16) int2 g_rec[MAXP];        // (src, eid), dst-grouped, 8-aligned segs
__device__ float g_y[(size_t)(MAXN + 1) * NF];    // row MAXN stays all-zero (pad target)

// ---------------- packed f32x2 helpers ----------------
__device__ __forceinline__ void ffma2(u64 &d, u64 a, u64 b) {
    asm("fma.rn.f32x2 %0, %1, %2, %0;" : "+l"(d) : "l"(a), "l"(b));
}
__device__ __forceinline__ u64 pack2(float lo, float hi) {
    u64 r;
    asm("mov.b64 %0, {%1, %2};" : "=l"(r) : "f"(lo), "f"(hi));
    return r;
}
__device__ __forceinline__ void unpack2(float &lo, float &hi, u64 v) {
    asm("mov.b64 {%0, %1}, %2;" : "=f"(lo), "=f"(hi) : "l"(v));
}

// ---------------- grid barrier (monotonic, replay-safe) ----------------
__device__ __forceinline__ void gridbar(int NB) {
    __syncthreads();
    if (threadIdx.x == 0) {
        __threadfence();
        int old = atomicAdd(&g_bar, 1);
        int target = (old / NB + 1) * NB;
        while (*(volatile int*)&g_bar < target) { }
        __threadfence();
    }
    __syncthreads();
}

// ---------------- build: hist + padded scan + cursor (one kernel) ----------------
__global__ void __launch_bounds__(BLD_B) k_build(const int* __restrict__ dst, int E, int N, int NB) {
    int t = threadIdx.x, b = blockIdx.x;
    int tid = b * BLD_B + t;
    int T = NB * BLD_B;

    // hist (grid-stride, int4)
    int nv = E >> 2;
    for (int q = tid; q < nv; q += T) {
        int4 d = ((const int4*)dst)[q];
        atomicAdd(&g_deg[d.x], 1);
        atomicAdd(&g_deg[d.y], 1);
        atomicAdd(&g_deg[d.z], 1);
        atomicAdd(&g_deg[d.w], 1);
    }
    for (int e = (nv << 2) + tid; e < E; e += T) atomicAdd(&g_deg[dst[e]], 1);

    gridbar(NB);

    // per-block inclusive scan of padded degrees
    __shared__ int sh[BLD_B];
    __shared__ int s_boff;
    int i = b * BLD_B + t;
    int v = (i < N) ? ((g_deg[i] + 7) & ~7) : 0;
    sh[t] = v;
    __syncthreads();
    for (int d = 1; d < BLD_B; d <<= 1) {
        int u = (t >= d) ? sh[t - d] : 0;
        __syncthreads();
        sh[t] += u;
        __syncthreads();
    }
    int loc = sh[t] - v;                       // exclusive local prefix
    if (t == BLD_B - 1) g_bsum[b] = sh[BLD_B - 1];

    gridbar(NB);

    if (t == 0) {
        int s = 0;
        for (int k = 0; k < b; k++) s += g_bsum[k];
        s_boff = s;
        if (b == 0) {
            int tot = 0;
            for (int k = 0; k < NB; k++) tot += g_bsum[k];
            g_off[N] = tot;
        }
    }
    __syncthreads();
    if (i < N) {
        int o = loc + s_boff;
        g_off[i] = o;
        g_cur[i] = o;
    }
}

// ---------------- scatter: (src, eid) records + pads ----------------
__global__ void k_scatter(const int* __restrict__ src, const int* __restrict__ dst,
                          int E, int N) {
    int t = blockIdx.x * blockDim.x + threadIdx.x;
    if (t < E) {
        int pos = atomicAdd(&g_cur[dst[t]], 1);
        g_rec[pos] = make_int2(src[t], t);
    } else {
        int idx = t - E;
        int i = idx >> 3, s = idx & 7;
        if (i < N) {
            int p = g_off[i] + g_deg[i] + s;
            if (p < g_off[i + 1]) g_rec[p] = make_int2(N, 0);  // y[N]=0 row, ef[0] (x0)
        }
    }
}

// ---------------- y = X @ W^T : 64 nodes/block, 4 nodes/thread, wt fused ----------------
__global__ void __launch_bounds__(256) k_ygemm(const float* __restrict__ X,
                                               const float* __restrict__ W, int N) {
    __shared__ float WsT[NF * 68];    // pitch 68: float4-aligned, conflict-free reads
    __shared__ float xs[64][NF];
    int t = threadIdx.x;
    int base = blockIdx.x * 64;

    // transpose W (row-major [o][i]) into WsT[i*68+o]; coalesced global reads
    #pragma unroll
    for (int k = 0; k < 16; k++) {
        int idx = t + k * 256;                 // 4096 elements
        int o = idx >> 6, i = idx & 63;
        WsT[i * 68 + o] = W[idx];
    }
    #pragma unroll
    for (int k = 0; k < 4; k++) {
        int idx = t + k * 256;
        int ln = idx >> 4, q = idx & 15;
        int n = base + ln;
        float4 v = (n < N) ? ((const float4*)(X + (size_t)n * NF))[q]
                           : make_float4(0.f, 0.f, 0.f, 0.f);
        ((float4*)&xs[ln][0])[q] = v;
    }
    __syncthreads();

    int o4 = (t & 15) * 4;
    int slot = t >> 4;
    float4 a0 = make_float4(0.f, 0.f, 0.f, 0.f);
    float4 a1 = a0, a2 = a0, a3 = a0;
    #pragma unroll 8
    for (int i = 0; i < NF; i++) {
        float4 w = *(const float4*)&WsT[i * 68 + o4];
        float x0 = xs[slot][i];
        float x1 = xs[slot + 16][i];
        float x2 = xs[slot + 32][i];
        float x3 = xs[slot + 48][i];
        a0.x += w.x * x0; a0.y += w.y * x0; a0.z += w.z * x0; a0.w += w.w * x0;
        a1.x += w.x * x1; a1.y += w.y * x1; a1.z += w.z * x1; a1.w += w.w * x1;
        a2.x += w.x * x2; a2.y += w.y * x2; a2.z += w.z * x2; a2.w += w.w * x2;
        a3.x += w.x * x3; a3.y += w.y * x3; a3.z += w.z * x3; a3.w += w.w * x3;
    }
    int n0 = base + slot;
    if (n0 < N)      *(float4*)(g_y + (size_t)n0 * NF + o4) = a0;
    if (n0 + 16 < N) *(float4*)(g_y + (size_t)(n0 + 16) * NF + o4) = a1;
    if (n0 + 32 < N) *(float4*)(g_y + (size_t)(n0 + 32) * NF + o4) = a2;
    if (n0 + 48 < N) *(float4*)(g_y + (size_t)(n0 + 48) * NF + o4) = a3;
}

// ---------------- main: warp-per-node, 8-edge batches, ef gathered ----------------
__device__ __forceinline__ void edge2(u64 (&acc)[8], float4 ea, float4 eb, float2 yv) {
    u64 yx  = pack2(yv.x, yv.x);
    u64 yy  = pack2(yv.y, yv.y);
    u64 e01 = pack2(ea.x, ea.y);
    u64 e23 = pack2(ea.z, ea.w);
    u64 e45 = pack2(eb.x, eb.y);
    u64 e67 = pack2(eb.z, eb.w);
    ffma2(acc[0], e01, yx); ffma2(acc[1], e01, yy);
    ffma2(acc[2], e23, yx); ffma2(acc[3], e23, yy);
    ffma2(acc[4], e45, yx); ffma2(acc[5], e45, yy);
    ffma2(acc[6], e67, yx); ffma2(acc[7], e67, yy);
}

__global__ void __launch_bounds__(256, 3) k_main(const float* __restrict__ ef,
                                                 const float* __restrict__ bvec,
                                                 float* __restrict__ out, int N) {
    int gid = blockIdx.x * blockDim.x + threadIdx.x;
    if (gid < N) g_deg[gid] = 0;          // zero for the NEXT invocation
    int w = gid >> 5;
    if (w >= N) return;
    int lane = threadIdx.x & 31;
    int beg = g_off[w], end = g_off[w + 1];   // multiples of 8

    u64 acc[8];
    #pragma unroll
    for (int a = 0; a < 8; a++) acc[a] = 0ull;

    const float* yb = g_y + lane * 2;

    for (int j = beg; j < end; j += 8) {
        const int4* rp = (const int4*)(g_rec + j);      // 64B-aligned
        int4 r01 = rp[0];   // (src0,eid0,src1,eid1)
        int4 r23 = rp[1];
        int4 r45 = rp[2];
        int4 r67 = rp[3];
        // 8 independent y gathers (coalesced 256B, L2-resident)
        float2 y0 = *(const float2*)(yb + (size_t)r01.x * NF);
        float2 y1 = *(const float2*)(yb + (size_t)r01.z * NF);
        float2 y2 = *(const float2*)(yb + (size_t)r23.x * NF);
        float2 y3 = *(const float2*)(yb + (size_t)r23.z * NF);
        float2 y4 = *(const float2*)(yb + (size_t)r45.x * NF);
        float2 y5 = *(const float2*)(yb + (size_t)r45.z * NF);
        float2 y6 = *(const float2*)(yb + (size_t)r67.x * NF);
        float2 y7 = *(const float2*)(yb + (size_t)r67.z * NF);
        // 8 ef rows (32B each = 2 broadcast LDG.128; random but single-sector)
        const float4* e0 = (const float4*)(ef + (size_t)r01.y * ED);
        const float4* e1 = (const float4*)(ef + (size_t)r01.w * ED);
        const float4* e2 = (const float4*)(ef + (size_t)r23.y * ED);
        const float4* e3 = (const float4*)(ef + (size_t)r23.w * ED);
        const float4* e4 = (const float4*)(ef + (size_t)r45.y * ED);
        const float4* e5 = (const float4*)(ef + (size_t)r45.w * ED);
        const float4* e6 = (const float4*)(ef + (size_t)r67.y * ED);
        const float4* e7 = (const float4*)(ef + (size_t)r67.w * ED);
        edge2(acc, e0[0], e0[1], y0);
        edge2(acc, e1[0], e1[1], y1);
        edge2(acc, e2[0], e2[1], y2);
        edge2(acc, e3[0], e3[1], y3);
        edge2(acc, e4[0], e4[1], y4);
        edge2(acc, e5[0], e5[1], y5);
        edge2(acc, e6[0], e6[1], y6);
        edge2(acc, e7[0], e7[1], y7);
    }

    float2 bb = *(const float2*)(bvec + lane * 2);
    float* op = out + (size_t)w * (ED * NF);
    #pragma unroll
    for (int p = 0; p < 4; p++) {
        float xk0, xk1, yk0, yk1;
        unpack2(xk0, xk1, acc[2 * p]);       // o_x for k=2p, 2p+1
        unpack2(yk0, yk1, acc[2 * p + 1]);   // o_y
        float2 v0, v1;
        v0.x = xk0 + bb.x;  v0.y = yk0 + bb.y;
        v1.x = xk1 + bb.x;  v1.y = yk1 + bb.y;
        *(float2*)(op + (2 * p) * NF + lane * 2)     = v0;
        *(float2*)(op + (2 * p + 1) * NF + lane * 2) = v1;
    }
}

// ---------------- launch ----------------

extern "C" void kernel_launch(void* const* d_in, const int* in_sizes, int n_in,
                              void* d_out, int out_size) {
    const float* node_feat = (const float*)d_in[0];
    const float* edge_feat = (const float*)d_in[1];
    const float* W         = (const float*)d_in[2];
    const float* b         = (const float*)d_in[3];
    const int*   src       = (const int*)d_in[4];
    const int*   dst       = (const int*)d_in[5];

    int N = in_sizes[0] / NF;     // 50000
    int E = in_sizes[4];          // 800000
    int NB = (N + BLD_B - 1) / BLD_B;   // 49 blocks (co-resident: grid-barrier safe)

    // Side stream for the (X,W)-only GEMM; event fork/join is capture-legal.
    cudaStream_t s2;
    cudaStreamCreateWithFlags(&s2, cudaStreamNonBlocking);
    cudaEvent_t evF, evJ;
    cudaEventCreateWithFlags(&evF, cudaEventDisableTiming);
    cudaEventCreateWithFlags(&evJ, cudaEventDisableTiming);

    cudaEventRecord(evF, 0);
    cudaStreamWaitEvent(s2, evF, 0);

    // Launch indices (ncu capture slot = 3 -> k_main):
    k_ygemm  <<<(N + 63) / 64, 256, 0, s2>>>(node_feat, W, N);        // 0
    cudaEventRecord(evJ, s2);
    k_build  <<<NB, BLD_B>>>(dst, E, N, NB);                          // 1
    k_scatter<<<(E + 8 * N + 255) / 256, 256>>>(src, dst, E, N);      // 2
    cudaStreamWaitEvent(0, evJ, 0);
    k_main   <<<(N * 32 + 255) / 256, 256>>>(edge_feat, b, (float*)d_out, N); // 3 <- profiled
}

// round 9
// speedup vs baseline: 1.1226x; 1.1226x over previous
#include <cuda_runtime.h>

// EfConv: out[n, k*64+o] = sum_{e: dst_e=n} ef[e,k] * (node_feat[src_e] . W[o]) + b[o]
// y = X @ W^T first (side stream). CSR-by-dst with 8-aligned segments; payload
// is (src, edge_id) int2 records; pads use src=N (extra all-zero y row), eid=0.
// R9: k_main stages records in smem (kills per-batch rec LDG latency, frees
// regs -> 4 CTAs/SM); k_build widened to 148 co-resident blocks.

#define MAXN 50000
#define MAXE 800000
#define NF 64
#define ED 8
#define MAXP (MAXE + 8 * MAXN)
#define BLD_B 1024
#define BLD_G 148
#define SEG_CAP 64              // staged records per node (multiple of 8)

typedef unsigned long long u64;

__device__ int   g_deg[MAXN];        // zeroed at load; re-zeroed by k_main for next call
__device__ int   g_off[MAXN + 1];
__device__ int   g_cur[MAXN];
__device__ int   g_bsum[BLD_G];
__device__ int   g_bar;              // monotonic grid-barrier counter (never reset)
__device__ __align__(16) int2 g_rec[MAXP];        // (src, eid), dst-grouped, 8-aligned segs
__device__ float g_y[(size_t)(MAXN + 1) * NF];    // row MAXN stays all-zero (pad target)

// ---------------- packed f32x2 helpers ----------------
__device__ __forceinline__ void ffma2(u64 &d, u64 a, u64 b) {
    asm("fma.rn.f32x2 %0, %1, %2, %0;" : "+l"(d) : "l"(a), "l"(b));
}
__device__ __forceinline__ u64 pack2(float lo, float hi) {
    u64 r;
    asm("mov.b64 %0, {%1, %2};" : "=l"(r) : "f"(lo), "f"(hi));
    return r;
}
__device__ __forceinline__ void unpack2(float &lo, float &hi, u64 v) {
    asm("mov.b64 {%0, %1}, %2;" : "=f"(lo), "=f"(hi) : "l"(v));
}

// ---------------- grid barrier (monotonic, replay-safe) ----------------
__device__ __forceinline__ void gridbar(int NB) {
    __syncthreads();
    if (threadIdx.x == 0) {
        __threadfence();
        int old = atomicAdd(&g_bar, 1);
        int target = (old / NB + 1) * NB;
        while (*(volatile int*)&g_bar < target) { }
        __threadfence();
    }
    __syncthreads();
}

// ---------------- build: hist + padded scan + cursor (one kernel, 148 blocks) ----------------
__global__ void __launch_bounds__(BLD_B) k_build(const int* __restrict__ dst, int E, int N) {
    int t = threadIdx.x, b = blockIdx.x;
    int tid = b * BLD_B + t;
    int T = BLD_G * BLD_B;

    // hist (grid-stride, int4)
    int nv = E >> 2;
    for (int q = tid; q < nv; q += T) {
        int4 d = ((const int4*)dst)[q];
        atomicAdd(&g_deg[d.x], 1);
        atomicAdd(&g_deg[d.y], 1);
        atomicAdd(&g_deg[d.z], 1);
        atomicAdd(&g_deg[d.w], 1);
    }
    for (int e = (nv << 2) + tid; e < E; e += T) atomicAdd(&g_deg[dst[e]], 1);

    gridbar(BLD_G);

    // per-block inclusive scan of padded degrees
    __shared__ int sh[BLD_B];
    __shared__ int s_boff;
    int i = tid;
    int v = (i < N) ? ((g_deg[i] + 7) & ~7) : 0;
    sh[t] = v;
    __syncthreads();
    for (int d = 1; d < BLD_B; d <<= 1) {
        int u = (t >= d) ? sh[t - d] : 0;
        __syncthreads();
        sh[t] += u;
        __syncthreads();
    }
    int loc = sh[t] - v;
    if (t == BLD_B - 1) g_bsum[b] = sh[BLD_B - 1];

    gridbar(BLD_G);

    if (t == 0) {
        int s = 0;
        for (int k = 0; k < b; k++) s += g_bsum[k];
        s_boff = s;
        if (b == 0) {
            int tot = 0;
            for (int k = 0; k < BLD_G; k++) tot += g_bsum[k];
            g_off[N] = tot;
        }
    }
    __syncthreads();
    if (i < N) {
        int o = loc + s_boff;
        g_off[i] = o;
        g_cur[i] = o;
    }
}

// ---------------- scatter: (src, eid) records + pads ----------------
__global__ void k_scatter(const int* __restrict__ src, const int* __restrict__ dst,
                          int E, int N) {
    int t = blockIdx.x * blockDim.x + threadIdx.x;
    if (t < E) {
        int pos = atomicAdd(&g_cur[dst[t]], 1);
        g_rec[pos] = make_int2(src[t], t);
    } else {
        int idx = t - E;
        int i = idx >> 3, s = idx & 7;
        if (i < N) {
            int p = g_off[i] + g_deg[i] + s;
            if (p < g_off[i + 1]) g_rec[p] = make_int2(N, 0);
        }
    }
}

// ---------------- y = X @ W^T : 64 nodes/block, 4 nodes/thread ----------------
__global__ void __launch_bounds__(256) k_ygemm(const float* __restrict__ X,
                                               const float* __restrict__ W, int N) {
    __shared__ float WsT[NF * 68];
    __shared__ float xs[64][NF];
    int t = threadIdx.x;
    int base = blockIdx.x * 64;

    #pragma unroll
    for (int k = 0; k < 16; k++) {
        int idx = t + k * 256;
        int o = idx >> 6, i = idx & 63;
        WsT[i * 68 + o] = W[idx];
    }
    #pragma unroll
    for (int k = 0; k < 4; k++) {
        int idx = t + k * 256;
        int ln = idx >> 4, q = idx & 15;
        int n = base + ln;
        float4 v = (n < N) ? ((const float4*)(X + (size_t)n * NF))[q]
                           : make_float4(0.f, 0.f, 0.f, 0.f);
        ((float4*)&xs[ln][0])[q] = v;
    }
    __syncthreads();

    int o4 = (t & 15) * 4;
    int slot = t >> 4;
    float4 a0 = make_float4(0.f, 0.f, 0.f, 0.f);
    float4 a1 = a0, a2 = a0, a3 = a0;
    #pragma unroll 8
    for (int i = 0; i < NF; i++) {
        float4 w = *(const float4*)&WsT[i * 68 + o4];
        float x0 = xs[slot][i];
        float x1 = xs[slot + 16][i];
        float x2 = xs[slot + 32][i];
        float x3 = xs[slot + 48][i];
        a0.x += w.x * x0; a0.y += w.y * x0; a0.z += w.z * x0; a0.w += w.w * x0;
        a1.x += w.x * x1; a1.y += w.y * x1; a1.z += w.z * x1; a1.w += w.w * x1;
        a2.x += w.x * x2; a2.y += w.y * x2; a2.z += w.z * x2; a2.w += w.w * x2;
        a3.x += w.x * x3; a3.y += w.y * x3; a3.z += w.z * x3; a3.w += w.w * x3;
    }
    int n0 = base + slot;
    if (n0 < N)      *(float4*)(g_y + (size_t)n0 * NF + o4) = a0;
    if (n0 + 16 < N) *(float4*)(g_y + (size_t)(n0 + 16) * NF + o4) = a1;
    if (n0 + 32 < N) *(float4*)(g_y + (size_t)(n0 + 32) * NF + o4) = a2;
    if (n0 + 48 < N) *(float4*)(g_y + (size_t)(n0 + 48) * NF + o4) = a3;
}

// ---------------- main: warp-per-node, records staged in smem ----------------
__device__ __forceinline__ void edge2(u64 (&acc)[8], float4 ea, float4 eb, float2 yv) {
    u64 yx  = pack2(yv.x, yv.x);
    u64 yy  = pack2(yv.y, yv.y);
    u64 e01 = pack2(ea.x, ea.y);
    u64 e23 = pack2(ea.z, ea.w);
    u64 e45 = pack2(eb.x, eb.y);
    u64 e67 = pack2(eb.z, eb.w);
    ffma2(acc[0], e01, yx); ffma2(acc[1], e01, yy);
    ffma2(acc[2], e23, yx); ffma2(acc[3], e23, yy);
    ffma2(acc[4], e45, yx); ffma2(acc[5], e45, yy);
    ffma2(acc[6], e67, yx); ffma2(acc[7], e67, yy);
}

// batch of 8 from 4 int4 recs
__device__ __forceinline__ void batch8(u64 (&acc)[8], const float* __restrict__ ef,
                                       const float* yb, int4 r01, int4 r23,
                                       int4 r45, int4 r67) {
    float2 y0 = *(const float2*)(yb + (size_t)r01.x * NF);
    float2 y1 = *(const float2*)(yb + (size_t)r01.z * NF);
    float2 y2 = *(const float2*)(yb + (size_t)r23.x * NF);
    float2 y3 = *(const float2*)(yb + (size_t)r23.z * NF);
    float2 y4 = *(const float2*)(yb + (size_t)r45.x * NF);
    float2 y5 = *(const float2*)(yb + (size_t)r45.z * NF);
    float2 y6 = *(const float2*)(yb + (size_t)r67.x * NF);
    float2 y7 = *(const float2*)(yb + (size_t)r67.z * NF);
    const float4* e0 = (const float4*)(ef + (size_t)r01.y * ED);
    const float4* e1 = (const float4*)(ef + (size_t)r01.w * ED);
    const float4* e2 = (const float4*)(ef + (size_t)r23.y * ED);
    const float4* e3 = (const float4*)(ef + (size_t)r23.w * ED);
    const float4* e4 = (const float4*)(ef + (size_t)r45.y * ED);
    const float4* e5 = (const float4*)(ef + (size_t)r45.w * ED);
    const float4* e6 = (const float4*)(ef + (size_t)r67.y * ED);
    const float4* e7 = (const float4*)(ef + (size_t)r67.w * ED);
    edge2(acc, e0[0], e0[1], y0);
    edge2(acc, e1[0], e1[1], y1);
    edge2(acc, e2[0], e2[1], y2);
    edge2(acc, e3[0], e3[1], y3);
    edge2(acc, e4[0], e4[1], y4);
    edge2(acc, e5[0], e5[1], y5);
    edge2(acc, e6[0], e6[1], y6);
    edge2(acc, e7[0], e7[1], y7);
}

__global__ void __launch_bounds__(256, 4) k_main(const float* __restrict__ ef,
                                                 const float* __restrict__ bvec,
                                                 float* __restrict__ out, int N) {
    __shared__ __align__(16) int2 srec[8][SEG_CAP];
    int gid = blockIdx.x * blockDim.x + threadIdx.x;
    if (gid < N) g_deg[gid] = 0;          // for the NEXT invocation
    int wid = threadIdx.x >> 5;
    int lane = threadIdx.x & 31;
    int w = blockIdx.x * 8 + wid;
    if (w >= N) return;

    float2 bb = *(const float2*)(bvec + lane * 2);     // early, independent
    int beg = g_off[w], end = g_off[w + 1];            // multiples of 8
    int len = end - beg;
    int cnt = (len < SEG_CAP) ? len : SEG_CAP;

    // stage records: two coalesced 256B loads
    if (lane < cnt)      srec[wid][lane]      = g_rec[beg + lane];
    if (lane + 32 < cnt) srec[wid][lane + 32] = g_rec[beg + lane + 32];
    __syncwarp();

    u64 acc[8];
    #pragma unroll
    for (int a = 0; a < 8; a++) acc[a] = 0ull;

    const float* yb = g_y + lane * 2;

    for (int j = 0; j < cnt; j += 8) {
        const int4* rp = (const int4*)&srec[wid][j];   // broadcast LDS
        batch8(acc, ef, yb, rp[0], rp[1], rp[2], rp[3]);
    }
    // overflow (rare: degree > SEG_CAP)
    for (int j = beg + SEG_CAP; j < end; j += 8) {
        const int4* rp = (const int4*)(g_rec + j);
        batch8(acc, ef, yb, rp[0], rp[1], rp[2], rp[3]);
    }

    float* op = out + (size_t)w * (ED * NF);
    #pragma unroll
    for (int p = 0; p < 4; p++) {
        float xk0, xk1, yk0, yk1;
        unpack2(xk0, xk1, acc[2 * p]);
        unpack2(yk0, yk1, acc[2 * p + 1]);
        float2 v0, v1;
        v0.x = xk0 + bb.x;  v0.y = yk0 + bb.y;
        v1.x = xk1 + bb.x;  v1.y = yk1 + bb.y;
        *(float2*)(op + (2 * p) * NF + lane * 2)     = v0;
        *(float2*)(op + (2 * p + 1) * NF + lane * 2) = v1;
    }
}

// ---------------- launch ----------------

extern "C" void kernel_launch(void* const* d_in, const int* in_sizes, int n_in,
                              void* d_out, int out_size) {
    const float* node_feat = (const float*)d_in[0];
    const float* edge_feat = (const float*)d_in[1];
    const float* W         = (const float*)d_in[2];
    const float* b         = (const float*)d_in[3];
    const int*   src       = (const int*)d_in[4];
    const int*   dst       = (const int*)d_in[5];

    int N = in_sizes[0] / NF;     // 50000
    int E = in_sizes[4];          // 800000

    // Side stream for the (X,W)-only GEMM; event fork/join is capture-legal.
    cudaStream_t s2;
    cudaStreamCreateWithFlags(&s2, cudaStreamNonBlocking);
    cudaEvent_t evF, evJ;
    cudaEventCreateWithFlags(&evF, cudaEventDisableTiming);
    cudaEventCreateWithFlags(&evJ, cudaEventDisableTiming);

    cudaEventRecord(evF, 0);
    cudaStreamWaitEvent(s2, evF, 0);

    // Launch indices (ncu capture slot = 3 -> k_main):
    k_ygemm  <<<(N + 63) / 64, 256, 0, s2>>>(node_feat, W, N);        // 0
    cudaEventRecord(evJ, s2);
    k_build  <<<BLD_G, BLD_B>>>(dst, E, N);                           // 1
    k_scatter<<<(E + 8 * N + 255) / 256, 256>>>(src, dst, E, N);      // 2
    cudaStreamWaitEvent(0, evJ, 0);
    k_main   <<<(N + 7) / 8, 256>>>(edge_feat, b, (float*)d_out, N);  // 3 <- profiled
}